// round 3
// baseline (speedup 1.0000x reference)
#include <cuda_runtime.h>

#define NB 8
#define ND 512
#define NN 1024
#define NH 8
#define KD 64

// Scratch (device globals; no runtime allocation allowed)
__device__ float g_q[NB * NN * ND];     // [b][n][h*64+k]
__device__ float g_k[NB * NN * KD];     // [b][m][k]
__device__ float g_v[NB * NN * KD];     // [b][m][v]
__device__ float g_o[NB * NN * ND];     // [b][n][h*64+v]
__device__ float g_wkv[128 * ND];       // packed [j][d]: j<64 -> key_proj, else value_proj

// ---------------------------------------------------------------------------
// Kernel 1: pack key_proj [D, 64] and value_proj [D, 64] into row-major [j][d]
// ---------------------------------------------------------------------------
__global__ void pack_wkv_kernel(const float* __restrict__ kp,
                                const float* __restrict__ vp) {
    int idx = blockIdx.x * 256 + threadIdx.x;   // 0 .. 128*512-1
    int j = idx >> 9;
    int d = idx & 511;
    g_wkv[idx] = (j < 64) ? kp[d * 64 + j] : vp[d * 64 + (j - 64)];
}

// ---------------------------------------------------------------------------
// Kernel 2: fused QKV projection.
// C[b][n][j] = sum_d x[b][d][n] * W[j][d],  j in [0, 640)
//   j <  512 : W = query_proj (already [j][d] row-major)
//   j >= 512 : W = g_wkv[j-512]
// Tile 64(n) x 64(j), K-chunk 32, 256 threads, 4x4 per thread.
// ---------------------------------------------------------------------------
__global__ void qkv_gemm_kernel(const float* __restrict__ x,
                                const float* __restrict__ wq) {
    int b  = blockIdx.z;
    int n0 = blockIdx.y * 64;
    int j0 = blockIdx.x * 64;
    const float* xb = x + (size_t)b * ND * NN;

    __shared__ float As[32][64];    // [dd][nn]
    __shared__ float Bs[32][65];    // [dd][jj] (+1 pad kills STS conflicts)

    int tid = threadIdx.x;
    int tx = tid & 15, ty = tid >> 4;
    float acc[4][4] = {};

    for (int d0 = 0; d0 < ND; d0 += 32) {
        // Load x tile: 32x64 floats, float4 along n (coalesced)
        #pragma unroll
        for (int r = 0; r < 2; r++) {
            int f4 = tid + 256 * r;              // 0..511
            int dd = f4 >> 4, c4 = (f4 & 15) << 2;
            *(float4*)&As[dd][c4] =
                *(const float4*)&xb[(size_t)(d0 + dd) * NN + n0 + c4];
        }
        // Load W tile: scalar, coalesced along d
        #pragma unroll
        for (int r = 0; r < 8; r++) {
            int lid = tid + 256 * r;             // 0..2047
            int dd = lid & 31, jj = lid >> 5;
            int j = j0 + jj;
            const float* wrow = (j < 512) ? (wq + (size_t)j * ND)
                                          : (g_wkv + (size_t)(j - 512) * ND);
            Bs[dd][jj] = wrow[d0 + dd];
        }
        __syncthreads();

        #pragma unroll
        for (int dd = 0; dd < 32; dd++) {
            float4 av = *(const float4*)&As[dd][ty << 2];
            float a0 = av.x, a1 = av.y, a2 = av.z, a3 = av.w;
            float bb[4];
            #pragma unroll
            for (int l = 0; l < 4; l++) bb[l] = Bs[dd][(tx << 2) + l];
            acc[0][0] += a0 * bb[0]; acc[0][1] += a0 * bb[1];
            acc[0][2] += a0 * bb[2]; acc[0][3] += a0 * bb[3];
            acc[1][0] += a1 * bb[0]; acc[1][1] += a1 * bb[1];
            acc[1][2] += a1 * bb[2]; acc[1][3] += a1 * bb[3];
            acc[2][0] += a2 * bb[0]; acc[2][1] += a2 * bb[1];
            acc[2][2] += a2 * bb[2]; acc[2][3] += a2 * bb[3];
            acc[3][0] += a3 * bb[0]; acc[3][1] += a3 * bb[1];
            acc[3][2] += a3 * bb[2]; acc[3][3] += a3 * bb[3];
        }
        __syncthreads();
    }

    // Write out: Q / K / V split by j (uniform per block since tiles are 64-wide)
    #pragma unroll
    for (int i = 0; i < 4; i++) {
        int n = n0 + (ty << 2) + i;
        #pragma unroll
        for (int l = 0; l < 4; l++) {
            int j = j0 + (tx << 2) + l;
            float val = acc[i][l];
            if (j < 512)      g_q[((size_t)(b * NN + n)) * ND + j] = val;
            else if (j < 576) g_k[((size_t)(b * NN + n)) * KD + (j - 512)] = val;
            else              g_v[((size_t)(b * NN + n)) * KD + (j - 576)] = val;
        }
    }
}

// ---------------------------------------------------------------------------
// Kernel 3: flash-style attention. One query row per thread, 128 threads/CTA.
// Grid: (8 q-blocks, 8 heads, 8 batch). K/V staged in smem 64 rows at a time;
// all smem compute reads are uniform across the warp (broadcast, conflict-free).
// ---------------------------------------------------------------------------
__global__ void __launch_bounds__(128, 1) attn_kernel() {
    int b = blockIdx.z, h = blockIdx.y;
    int n = blockIdx.x * 128 + threadIdx.x;

    __shared__ float Ks[64 * 64];
    __shared__ float Vs[64 * 64];

    float q[64];
    const float4* qp =
        (const float4*)(g_q + ((size_t)(b * NN + n)) * ND + h * KD);
    #pragma unroll
    for (int i = 0; i < 16; i++) {
        float4 t = qp[i];
        q[4*i+0] = t.x * 0.125f;   // fold softmax scale 1/sqrt(64)
        q[4*i+1] = t.y * 0.125f;
        q[4*i+2] = t.z * 0.125f;
        q[4*i+3] = t.w * 0.125f;
    }

    float o[64];
    #pragma unroll
    for (int v = 0; v < 64; v++) o[v] = 0.0f;
    float mrow = -1e30f, lsum = 0.0f;

    for (int mb = 0; mb < 16; mb++) {
        __syncthreads();
        const float4* kp = (const float4*)(g_k + (size_t)(b * NN + mb * 64) * KD);
        const float4* vp = (const float4*)(g_v + (size_t)(b * NN + mb * 64) * KD);
        #pragma unroll
        for (int r = 0; r < 8; r++) {
            int lid = threadIdx.x + 128 * r;     // 1024 float4 per tile
            ((float4*)Ks)[lid] = kp[lid];
            ((float4*)Vs)[lid] = vp[lid];
        }
        __syncthreads();

        #pragma unroll
        for (int c = 0; c < 2; c++) {
            float s[32];
            float bm = -1e30f;
            #pragma unroll
            for (int j = 0; j < 32; j++) {
                const float4* kr = (const float4*)(Ks + (c * 32 + j) * 64);
                float acc = 0.0f;
                #pragma unroll
                for (int d4 = 0; d4 < 16; d4++) {
                    float4 kv = kr[d4];
                    acc += q[4*d4+0] * kv.x + q[4*d4+1] * kv.y
                         + q[4*d4+2] * kv.z + q[4*d4+3] * kv.w;
                }
                s[j] = acc;
                bm = fmaxf(bm, acc);
            }
            if (bm > mrow) {
                float corr = __expf(mrow - bm);
                mrow = bm;
                lsum *= corr;
                #pragma unroll
                for (int v = 0; v < 64; v++) o[v] *= corr;
            }
            #pragma unroll
            for (int j = 0; j < 32; j++) {
                float p = __expf(s[j] - mrow);
                lsum += p;
                const float4* vr = (const float4*)(Vs + (c * 32 + j) * 64);
                #pragma unroll
                for (int v4 = 0; v4 < 16; v4++) {
                    float4 vv = vr[v4];
                    o[4*v4+0] += p * vv.x;
                    o[4*v4+1] += p * vv.y;
                    o[4*v4+2] += p * vv.z;
                    o[4*v4+3] += p * vv.w;
                }
            }
        }
    }

    float inv = 1.0f / lsum;
    float* op = g_o + ((size_t)(b * NN + n)) * ND + h * KD;
    #pragma unroll
    for (int v4 = 0; v4 < 16; v4++) {
        float4 t;
        t.x = o[4*v4+0] * inv; t.y = o[4*v4+1] * inv;
        t.z = o[4*v4+2] * inv; t.w = o[4*v4+3] * inv;
        ((float4*)op)[v4] = t;
    }
}

// ---------------------------------------------------------------------------
// Kernel 4: output projection.
// out[b][dout][n] = sum_j out_proj[dout][j] * g_o[b][n][j]   (j = h*64+v)
// Tile 64(dout) x 64(n), K-chunk 32 over j.
// ---------------------------------------------------------------------------
__global__ void out_gemm_kernel(const float* __restrict__ wout,
                                float* __restrict__ out) {
    int b   = blockIdx.z;
    int do0 = blockIdx.y * 64;
    int n0  = blockIdx.x * 64;

    __shared__ float Ws[64][36];   // [dout_local][jj] (pad 36, float4-aligned)
    __shared__ float Os[64][36];   // [n_local][jj]

    int tid = threadIdx.x;
    int tx = tid & 15, ty = tid >> 4;
    float acc[4][4] = {};

    const float* ob = g_o + (size_t)b * NN * ND;

    for (int j0 = 0; j0 < ND; j0 += 32) {
        #pragma unroll
        for (int r = 0; r < 2; r++) {
            int f4 = tid + 256 * r;              // 512 float4 per tile
            int row = f4 >> 3, c4 = (f4 & 7) << 2;
            *(float4*)&Ws[row][c4] =
                *(const float4*)&wout[(size_t)(do0 + row) * ND + j0 + c4];
            *(float4*)&Os[row][c4] =
                *(const float4*)&ob[(size_t)(n0 + row) * ND + j0 + c4];
        }
        __syncthreads();

        #pragma unroll
        for (int jj = 0; jj < 32; jj++) {
            float a[4], bb[4];
            #pragma unroll
            for (int i = 0; i < 4; i++) a[i] = Ws[(ty << 2) + i][jj];
            #pragma unroll
            for (int l = 0; l < 4; l++) bb[l] = Os[(tx << 2) + l][jj];
            #pragma unroll
            for (int i = 0; i < 4; i++)
                #pragma unroll
                for (int l = 0; l < 4; l++) acc[i][l] += a[i] * bb[l];
        }
        __syncthreads();
    }

    #pragma unroll
    for (int i = 0; i < 4; i++) {
        int dd = do0 + (ty << 2) + i;
        float4 t;
        t.x = acc[i][0]; t.y = acc[i][1]; t.z = acc[i][2]; t.w = acc[i][3];
        *(float4*)&out[((size_t)b * ND + dd) * NN + n0 + (tx << 2)] = t;
    }
}

// ---------------------------------------------------------------------------
// Launch
// ---------------------------------------------------------------------------
extern "C" void kernel_launch(void* const* d_in, const int* in_sizes, int n_in,
                              void* d_out, int out_size) {
    const float* x     = (const float*)d_in[0];  // [8, 512, 32, 32]
    const float* wq    = (const float*)d_in[1];  // [8, 64, 512]
    const float* wk    = (const float*)d_in[2];  // [512, 64]
    const float* wv    = (const float*)d_in[3];  // [512, 64]
    const float* wo    = (const float*)d_in[4];  // [512, 8, 64]
    float* out         = (float*)d_out;          // [8, 512, 32, 32]

    pack_wkv_kernel<<<256, 256>>>(wk, wv);
    qkv_gemm_kernel<<<dim3(10, 16, NB), 256>>>(x, wq);
    attn_kernel<<<dim3(8, NH, NB), 128>>>();
    out_gemm_kernel<<<dim3(16, 8, NB), 256>>>(wo, out);
}